// round 1
// baseline (speedup 1.0000x reference)
#include <cuda_runtime.h>

#define BATCH 1024
#define FDIM 32
#define EMBED 8
#define HEADS 4
#define NBINS 1100
#define OUTD 16
#define FH (FDIM*HEADS)

// Scratch (allocation-free: __device__ globals)
__device__ float2 g_q[FH * BATCH];
__device__ float2 g_k[FH * BATCH];
__device__ float2 g_v[FH * BATCH];
__device__ float4 g_o4[BATCH * FDIM * EMBED / 4];   // [B][256] floats

// Replicate jnp.linspace(MN,MX,NBINS) element: start + step*i with fp32
// rounding at each op (no FMA contraction).
__device__ __forceinline__ float binv(int i) {
    const float step = 301.0f / 1099.0f;   // fp32 division, same as JAX
    return __fadd_rn(__fmul_rn(step, (float)i), -1.0f);
}

// ---------------------------------------------------------------------------
// Stage A: bin search + embedding gather + QKV projection
// grid (4, 32) x 256 threads : blockIdx.y = f, threads cover 256 consecutive b
// ---------------------------------------------------------------------------
__global__ void stageA(const float* __restrict__ x, const float* __restrict__ emb,
                       const float* __restrict__ ipw, const float* __restrict__ ipb) {
    __shared__ float sw[192];
    __shared__ float sb[24];
    int tid = threadIdx.x;
    if (tid < 192) sw[tid] = ipw[tid];
    if (tid < 24)  sb[tid] = ipb[tid];
    __syncthreads();

    int f = blockIdx.y;
    int b = blockIdx.x * blockDim.x + tid;

    float xv = x[b * FDIM + f];
    float xc = fminf(fmaxf(xv, -1.0f), 300.0f);

    // searchsorted(bins, xc, 'left'): first i with bins[i] >= xc
    int i = (int)((xc + 1.0f) * (1099.0f / 301.0f));
    i = max(0, min(i, NBINS - 1));
    while (i > 0 && binv(i - 1) >= xc) --i;
    while (i < NBINS - 1 && binv(i) < xc) ++i;

    const float4* ep = (const float4*)(emb + ((size_t)f * NBINS + i) * EMBED);
    float4 e0 = ep[0], e1 = ep[1];
    float xe[8] = {e0.x, e0.y, e0.z, e0.w, e1.x, e1.y, e1.z, e1.w};

    float out[24];
#pragma unroll
    for (int r = 0; r < 24; ++r) {
        float acc = sb[r];
#pragma unroll
        for (int j = 0; j < 8; ++j) acc = fmaf(xe[j], sw[r * 8 + j], acc);
        out[r] = acc;
    }

#pragma unroll
    for (int h = 0; h < HEADS; ++h) {
        int o = (f * HEADS + h) * BATCH + b;
        g_q[o] = make_float2(out[h * 2],      out[h * 2 + 1]);
        g_k[o] = make_float2(out[8 + h * 2],  out[8 + h * 2 + 1]);
        g_v[o] = make_float2(out[16 + h * 2], out[16 + h * 2 + 1]);
    }
}

// ---------------------------------------------------------------------------
// Stage B: per-(f,h) attention over batch axis, hd=2, single-pass softmax
// grid (128, 4) x 256 threads : blockIdx.x = f*4+h, blockIdx.y = b-chunk
// ---------------------------------------------------------------------------
__global__ void stageB() {
    __shared__ float4 kv[BATCH];   // (k0,k1,v0,v1) per c : 16KB
    int fh  = blockIdx.x;
    int tid = threadIdx.x;

    for (int c = tid; c < BATCH; c += blockDim.x) {
        float2 k = g_k[fh * BATCH + c];
        float2 v = g_v[fh * BATCH + c];
        kv[c] = make_float4(k.x, k.y, v.x, v.y);
    }
    __syncthreads();

    int b = blockIdx.y * blockDim.x + tid;
    float2 q = g_q[fh * BATCH + b];
    // fold 1/sqrt(hd) and log2(e) into q so exp(s) == exp2(q'.k)
    const float C = 1.4426950408889634f * 0.70710678118654752f;
    float q0 = q.x * C, q1 = q.y * C;

    float den = 0.f, a0 = 0.f, a1 = 0.f;
#pragma unroll 8
    for (int c = 0; c < BATCH; ++c) {
        float4 t = kv[c];
        float s = fmaf(q0, t.x, q1 * t.y);
        float e;
        asm("ex2.approx.ftz.f32 %0, %1;" : "=f"(e) : "f"(s));
        den += e;
        a0 = fmaf(e, t.z, a0);
        a1 = fmaf(e, t.w, a1);
    }
    float inv = 1.0f / den;
    int f = fh >> 2, h = fh & 3;
    float* op = ((float*)g_o4) + (size_t)b * (FDIM * EMBED) + f * EMBED + h * 2;
    op[0] = a0 * inv;
    op[1] = a1 * inv;
}

// ---------------------------------------------------------------------------
// Stage C: out_proj (8x8 per f) + linear (16x256) + softmax(16)
// grid 64 x 512 threads : one warp per batch row, lane = f
// ---------------------------------------------------------------------------
__global__ void stageC(const float* __restrict__ opw, const float* __restrict__ opb,
                       const float* __restrict__ lw,  const float* __restrict__ lb,
                       float* __restrict__ out) {
    __shared__ float sWo[64];
    __shared__ float sbo[8];
    __shared__ float sLw[256 * 16];     // transposed: [i][t]
    __shared__ float sLb[16];
    __shared__ float o2sh[16][256];     // one 256-vector per warp

    int tid = threadIdx.x;
    for (int idx = tid; idx < 256 * 16; idx += blockDim.x) {
        int i = idx >> 4, t = idx & 15;
        sLw[idx] = lw[t * 256 + i];
    }
    if (tid < 64) sWo[tid] = opw[tid];
    if (tid < 8)  sbo[tid] = opb[tid];
    if (tid < 16) sLb[tid] = lb[tid];
    __syncthreads();

    int w = tid >> 5, lane = tid & 31;
    int b = blockIdx.x * 16 + w;

    // lane l owns feature f = l
    const float4* op = (const float4*)(((float*)g_o4) + (size_t)b * 256 + lane * 8);
    float4 v0 = op[0], v1 = op[1];
    float o[8] = {v0.x, v0.y, v0.z, v0.w, v1.x, v1.y, v1.z, v1.w};

#pragma unroll
    for (int e = 0; e < 8; ++e) {
        float acc = sbo[e];
#pragma unroll
        for (int j = 0; j < 8; ++j) acc = fmaf(o[j], sWo[e * 8 + j], acc);
        o2sh[w][lane * 8 + e] = acc;
    }
    __syncwarp();

    if (lane < 16) {
        float acc = sLb[lane];
#pragma unroll 8
        for (int i = 0; i < 256; ++i)
            acc = fmaf(o2sh[w][i], sLw[i * 16 + lane], acc);

        // softmax over 16 lanes
        float m = acc;
#pragma unroll
        for (int off = 8; off; off >>= 1)
            m = fmaxf(m, __shfl_xor_sync(0xffffu, m, off, 16));
        float e = __expf(acc - m);
        float s = e;
#pragma unroll
        for (int off = 8; off; off >>= 1)
            s += __shfl_xor_sync(0xffffu, s, off, 16);
        out[b * OUTD + lane] = e / s;
    }
}

// ---------------------------------------------------------------------------
extern "C" void kernel_launch(void* const* d_in, const int* in_sizes, int n_in,
                              void* d_out, int out_size) {
    const float* x   = (const float*)d_in[0];   // (1024, 32)
    const float* emb = (const float*)d_in[1];   // (32, 1100, 8)
    const float* ipw = (const float*)d_in[2];   // (24, 8)
    const float* ipb = (const float*)d_in[3];   // (24,)
    const float* opw = (const float*)d_in[4];   // (8, 8)
    const float* opb = (const float*)d_in[5];   // (8,)
    const float* lw  = (const float*)d_in[6];   // (16, 256)
    const float* lb  = (const float*)d_in[7];   // (16,)
    float* out = (float*)d_out;                 // (1024, 16)

    stageA<<<dim3(BATCH / 256, FDIM), 256>>>(x, emb, ipw, ipb);
    stageB<<<dim3(FH, BATCH / 256), 256>>>();
    stageC<<<BATCH / 16, 512>>>(opw, opb, lw, lb, out);
}

// round 2
// speedup vs baseline: 1.1224x; 1.1224x over previous
#include <cuda_runtime.h>

#define BATCH 1024
#define FDIM 32
#define EMBED 8
#define HEADS 4
#define NBINS 1100
#define OUTD 16
#define FH (FDIM*HEADS)

typedef unsigned long long u64;

// Scratch (allocation-free: __device__ globals)
__device__ float2 g_q[FH * BATCH];
__device__ float2 g_k[FH * BATCH];
__device__ float2 g_v[FH * BATCH];
__device__ float g_o[BATCH * FDIM * EMBED];   // [B][256]

// ---- packed f32x2 helpers (Blackwell FFMA2 path, PTX-only) -----------------
__device__ __forceinline__ u64 pk(float lo, float hi) {
    u64 r; asm("mov.b64 %0, {%1, %2};" : "=l"(r) : "f"(lo), "f"(hi)); return r;
}
__device__ __forceinline__ void upk(u64 a, float& x, float& y) {
    asm("mov.b64 {%0, %1}, %2;" : "=f"(x), "=f"(y) : "l"(a));
}
__device__ __forceinline__ u64 fma2(u64 a, u64 b, u64 c) {
    u64 d; asm("fma.rn.f32x2 %0, %1, %2, %3;" : "=l"(d) : "l"(a), "l"(b), "l"(c)); return d;
}
__device__ __forceinline__ u64 mul2(u64 a, u64 b) {
    u64 d; asm("mul.rn.f32x2 %0, %1, %2;" : "=l"(d) : "l"(a), "l"(b)); return d;
}
__device__ __forceinline__ u64 add2(u64 a, u64 b) {
    u64 d; asm("add.rn.f32x2 %0, %1, %2;" : "=l"(d) : "l"(a), "l"(b)); return d;
}
__device__ __forceinline__ float ex2f(float s) {
    float e; asm("ex2.approx.ftz.f32 %0, %1;" : "=f"(e) : "f"(s)); return e;
}

// Replicate jnp.linspace(MN,MX,NBINS) element: step*i + start, fp32 rounding
// at each op (no FMA contraction).
__device__ __forceinline__ float binv(int i) {
    const float step = 301.0f / 1099.0f;
    return __fadd_rn(__fmul_rn(step, (float)i), -1.0f);
}

// ---------------------------------------------------------------------------
// Stage A: bin search + embedding gather + QKV projection
// 64 blocks x 128 threads; each thread handles 4 consecutive f of one b
// (one LDG.128 for x, 8 independent emb gathers in flight -> MLP=8)
// ---------------------------------------------------------------------------
__global__ void stageA(const float* __restrict__ x, const float* __restrict__ emb,
                       const float* __restrict__ ipw, const float* __restrict__ ipb) {
    __shared__ float sw[192];
    __shared__ float sb[24];
    int tid = threadIdx.x;
    for (int i = tid; i < 192; i += 128) sw[i] = ipw[i];
    if (tid < 24) sb[tid] = ipb[tid];
    __syncthreads();

    int gt = blockIdx.x * 128 + tid;        // 0..8191
    int b  = gt >> 3;
    int fb = (gt & 7) << 2;                 // f base: 0,4,...,28

    float4 xv = *(const float4*)(x + b * FDIM + fb);
    float xs[4] = {xv.x, xv.y, xv.z, xv.w};

    int id[4];
#pragma unroll
    for (int j = 0; j < 4; ++j) {
        float xc = fminf(fmaxf(xs[j], -1.0f), 300.0f);
        int i = (int)((xc + 1.0f) * (1099.0f / 301.0f));
        i = max(0, min(i, NBINS - 1));
        while (i > 0 && binv(i - 1) >= xc) --i;
        while (i < NBINS - 1 && binv(i) < xc) ++i;
        id[j] = i;
        xs[j] = xc;
    }

    // Issue all 8 gather loads back-to-back (MLP=8)
    float4 e0[4], e1[4];
#pragma unroll
    for (int j = 0; j < 4; ++j) {
        const float4* ep = (const float4*)(emb + ((size_t)(fb + j) * NBINS + id[j]) * EMBED);
        e0[j] = ep[0];
        e1[j] = ep[1];
    }

#pragma unroll
    for (int j = 0; j < 4; ++j) {
        float xe[8] = {e0[j].x, e0[j].y, e0[j].z, e0[j].w,
                       e1[j].x, e1[j].y, e1[j].z, e1[j].w};
        float out[24];
#pragma unroll
        for (int r = 0; r < 24; ++r) {
            float acc = sb[r];
#pragma unroll
            for (int t = 0; t < 8; ++t) acc = fmaf(xe[t], sw[r * 8 + t], acc);
            out[r] = acc;
        }
        int f = fb + j;
#pragma unroll
        for (int h = 0; h < HEADS; ++h) {
            int o = (f * HEADS + h) * BATCH + b;
            g_q[o] = make_float2(out[h * 2],      out[h * 2 + 1]);
            g_k[o] = make_float2(out[8 + h * 2],  out[8 + h * 2 + 1]);
            g_v[o] = make_float2(out[16 + h * 2], out[16 + h * 2 + 1]);
        }
    }
}

// ---------------------------------------------------------------------------
// Stage B: per-(f,h) attention over batch axis, hd=2, single-pass softmax
// grid (128, 8) x 128 threads; packed f32x2 arithmetic over c-pairs
// ---------------------------------------------------------------------------
__global__ void stageB() {
    // per c-pair: sA = {pk(k0e,k0o), pk(k1e,k1o)}, sB = {pk(v0e,v0o), pk(v1e,v1o)}
    __shared__ ulonglong2 sA[BATCH / 2];   // 8KB
    __shared__ ulonglong2 sB[BATCH / 2];   // 8KB
    int fh  = blockIdx.x;
    int tid = threadIdx.x;

    const float4* kp = (const float4*)(g_k + fh * BATCH);  // (k0e,k1e,k0o,k1o)
    const float4* vp = (const float4*)(g_v + fh * BATCH);
    for (int p = tid; p < BATCH / 2; p += 128) {
        float4 k = kp[p];
        float4 v = vp[p];
        sA[p] = make_ulonglong2(pk(k.x, k.z), pk(k.y, k.w));
        sB[p] = make_ulonglong2(pk(v.x, v.z), pk(v.y, v.w));
    }
    __syncthreads();

    int b = blockIdx.y * 128 + tid;
    float2 q = g_q[fh * BATCH + b];
    // fold 1/sqrt(hd) and log2(e) into q so exp(s) == exp2(q'.k)
    const float C = 1.4426950408889634f * 0.70710678118654752f;
    float q0 = q.x * C, q1 = q.y * C;
    u64 qq0 = pk(q0, q0), qq1 = pk(q1, q1);
    u64 dd = pk(0.f, 0.f), aa0 = dd, aa1 = dd;

#pragma unroll 8
    for (int p = 0; p < BATCH / 2; ++p) {
        ulonglong2 A = sA[p];
        ulonglong2 B = sB[p];
        u64 ss = fma2(qq0, A.x, mul2(qq1, A.y));
        float s0, s1; upk(ss, s0, s1);
        u64 ee = pk(ex2f(s0), ex2f(s1));
        dd  = add2(dd, ee);
        aa0 = fma2(ee, B.x, aa0);
        aa1 = fma2(ee, B.y, aa1);
    }

    float d0, d1, a00, a01, a10, a11;
    upk(dd, d0, d1); upk(aa0, a00, a01); upk(aa1, a10, a11);
    float inv = 1.0f / (d0 + d1);
    int f = fh >> 2, h = fh & 3;
    float* op = g_o + (size_t)b * (FDIM * EMBED) + f * EMBED + h * 2;
    op[0] = (a00 + a01) * inv;
    op[1] = (a10 + a11) * inv;
}

// ---------------------------------------------------------------------------
// Stage C: out_proj (8x8 per f) + linear (16x256) + softmax(16)
// grid 64 x 512 threads : one warp per batch row, lane = f
// ---------------------------------------------------------------------------
__global__ void stageC(const float* __restrict__ opw, const float* __restrict__ opb,
                       const float* __restrict__ lw,  const float* __restrict__ lb,
                       float* __restrict__ out) {
    __shared__ float sWo[64];
    __shared__ float sbo[8];
    __shared__ float sLw[256 * 16];     // transposed: [i][t]
    __shared__ float sLb[16];
    __shared__ float o2sh[16][256];     // one 256-vector per warp

    int tid = threadIdx.x;
    for (int idx = tid; idx < 256 * 16; idx += blockDim.x) {
        int i = idx >> 4, t = idx & 15;
        sLw[idx] = lw[t * 256 + i];
    }
    if (tid < 64) sWo[tid] = opw[tid];
    if (tid < 8)  sbo[tid] = opb[tid];
    if (tid < 16) sLb[tid] = lb[tid];
    __syncthreads();

    int w = tid >> 5, lane = tid & 31;
    int b = blockIdx.x * 16 + w;

    // lane l owns feature f = l
    const float4* op = (const float4*)(g_o + (size_t)b * 256 + lane * 8);
    float4 v0 = op[0], v1 = op[1];
    float o[8] = {v0.x, v0.y, v0.z, v0.w, v1.x, v1.y, v1.z, v1.w};

#pragma unroll
    for (int e = 0; e < 8; ++e) {
        float acc = sbo[e];
#pragma unroll
        for (int j = 0; j < 8; ++j) acc = fmaf(o[j], sWo[e * 8 + j], acc);
        o2sh[w][lane * 8 + e] = acc;
    }
    __syncwarp();

    if (lane < 16) {
        float acc = sLb[lane];
#pragma unroll 8
        for (int i = 0; i < 256; ++i)
            acc = fmaf(o2sh[w][i], sLw[i * 16 + lane], acc);

        // softmax over 16 lanes
        float m = acc;
#pragma unroll
        for (int off = 8; off; off >>= 1)
            m = fmaxf(m, __shfl_xor_sync(0xffffu, m, off, 16));
        float e = __expf(acc - m);
        float s = e;
#pragma unroll
        for (int off = 8; off; off >>= 1)
            s += __shfl_xor_sync(0xffffu, s, off, 16);
        out[b * OUTD + lane] = e / s;
    }
}

// ---------------------------------------------------------------------------
extern "C" void kernel_launch(void* const* d_in, const int* in_sizes, int n_in,
                              void* d_out, int out_size) {
    const float* x   = (const float*)d_in[0];   // (1024, 32)
    const float* emb = (const float*)d_in[1];   // (32, 1100, 8)
    const float* ipw = (const float*)d_in[2];   // (24, 8)
    const float* ipb = (const float*)d_in[3];   // (24,)
    const float* opw = (const float*)d_in[4];   // (8, 8)
    const float* opb = (const float*)d_in[5];   // (8,)
    const float* lw  = (const float*)d_in[6];   // (16, 256)
    const float* lb  = (const float*)d_in[7];   // (16,)
    float* out = (float*)d_out;                 // (1024, 16)

    stageA<<<64, 128>>>(x, emb, ipw, ipb);
    stageB<<<dim3(FH, BATCH / 128), 128>>>();
    stageC<<<BATCH / 16, 512>>>(opw, opb, lw, lb, out);
}